// round 6
// baseline (speedup 1.0000x reference)
#include <cuda_runtime.h>
#include <math.h>
#include <stdint.h>

// NF4 quantize-dequantize, straight-through forward: out = data_type[idx]*s,
// s = per-row max|x| (clip 1e-6), idx = searchsorted(boundaries, x/s, left).
//
// R6: TMA-fed persistent pipeline. 296 blocks x 512 threads (2/SM). Rows are
// fetched global->shared with cp.async.bulk + mbarrier (zero register cost,
// full-rate MLP), double-buffered 32KB each. Pass B quantizes from smem (no
// L2 re-read). TMA for row r+GRID is in flight during row r's reduce/LUT/
// quantize, so DRAM reads overlap writes continuously.
//
// Exactness (unchanged, proven): thresholds T_j = largest float with
// RN(t/s) <= b_j (nextafter-refined) => (x/s > b_j) == (x > T_j) bit-exact.
// 258-cell LUT over u = x*(128/s)+129 via magic-FMA; cell width s/128 <<
// min threshold gap (~0.085*s) => <=1 threshold per cell. Entry = float4
// {T, vlo, vhi, pad}: one LDS.128 per element.

#define COLS   8192
#define NF4    2048          // float4 per row
#define ROWB   32768         // bytes per row
#define NT     512
#define CH     4             // float4 per thread per row (2048/512)
#define NB     15
#define NL     16
#define NCELL  258
#define GRID   296           // 2 blocks/SM x 148 SMs

// dynamic smem layout (bytes from base):
//   0    : mbar[2]            (16)
//   16   : Tsm[15]            (60)
//   80   : Vsm[16]            (64)
//   144  : wmax[16]           (64)
//   256  : table[258] float4  (4128)
//   4608 : buf0 (32768), 37376 : buf1 (32768)  -> total 70144
#define OFF_TSM   16
#define OFF_VSM   80
#define OFF_WMAX  144
#define OFF_TAB   256
#define OFF_BUF0  4608
#define OFF_BUF1  (4608 + ROWB)
#define SMEM_SZ   (OFF_BUF1 + ROWB)

__device__ __forceinline__ uint32_t smem_u32(const void* p) {
    uint32_t a;
    asm("{ .reg .u64 t; cvta.to.shared.u64 t, %1; cvt.u32.u64 %0, t; }"
        : "=r"(a) : "l"(p));
    return a;
}

__device__ __forceinline__ void mbar_init(uint32_t mbar, uint32_t cnt) {
    asm volatile("mbarrier.init.shared.b64 [%0], %1;" :: "r"(mbar), "r"(cnt) : "memory");
}
__device__ __forceinline__ void mbar_expect_tx(uint32_t mbar, uint32_t bytes) {
    asm volatile("mbarrier.arrive.expect_tx.shared.b64 _, [%0], %1;"
                 :: "r"(mbar), "r"(bytes) : "memory");
}
__device__ __forceinline__ void tma_bulk_g2s(uint32_t dst, const void* src,
                                             uint32_t bytes, uint32_t mbar) {
    asm volatile("cp.async.bulk.shared::cluster.global.mbarrier::complete_tx::bytes "
                 "[%0], [%1], %2, [%3];"
                 :: "r"(dst), "l"(src), "r"(bytes), "r"(mbar) : "memory");
}
__device__ __forceinline__ void mbar_wait(uint32_t mbar, uint32_t parity) {
    uint32_t done;
    asm volatile("{\n\t.reg .pred p;\n\t"
                 "mbarrier.try_wait.parity.acquire.cta.shared::cta.b64 p, [%1], %2;\n\t"
                 "selp.b32 %0, 1, 0, p;\n\t}"
                 : "=r"(done) : "r"(mbar), "r"(parity) : "memory");
    if (!done) {
        asm volatile("{\n\t.reg .pred P1;\n\t"
                     "W_%=:\n\t"
                     "mbarrier.try_wait.parity.acquire.cta.shared::cta.b64 P1, [%0], %1, 0x989680;\n\t"
                     "@P1 bra.uni D_%=;\n\t"
                     "bra.uni W_%=;\n\t"
                     "D_%=:\n\t}"
                     :: "r"(mbar), "r"(parity) : "memory");
    }
}

__global__ __launch_bounds__(NT, 2)
void nf4_kernel(const float* __restrict__ x,
                const float* __restrict__ bnd,
                const float* __restrict__ dt,
                float* __restrict__ out,
                int rows)
{
    extern __shared__ char smem[];
    float* Tsm  = (float*)(smem + OFF_TSM);
    float* Vsm  = (float*)(smem + OFF_VSM);
    float* wmax = (float*)(smem + OFF_WMAX);
    float4* table = (float4*)(smem + OFF_TAB);
    float4* buf0 = (float4*)(smem + OFF_BUF0);
    float4* buf1 = (float4*)(smem + OFF_BUF1);

    const int tid = threadIdx.x;
    const int lane = tid & 31;
    const uint32_t sbase = smem_u32(smem);
    const uint32_t mbarA0 = sbase;       // mbar for buf0
    const uint32_t mbarA1 = sbase + 8;   // mbar for buf1
    const float MAGIC = 8388608.0f + 129.0f;   // 2^23 + 129

    int r = blockIdx.x;
    if (r >= rows) return;

    if (tid == 0) {
        mbar_init(mbarA0, 1);
        mbar_init(mbarA1, 1);
    }
    __syncthreads();
    // prologue: fetch first row into buf0
    if (tid == 0) {
        mbar_expect_tx(mbarA0, ROWB);
        tma_bulk_g2s(sbase + OFF_BUF0, x + (size_t)r * COLS, ROWB, mbarA0);
    }

    int cur = 0;
    int phase0 = 0, phase1 = 0;

    while (true) {
        // ---- wait for current row data ----
        if (cur == 0) { mbar_wait(mbarA0, phase0); phase0 ^= 1; }
        else          { mbar_wait(mbarA1, phase1); phase1 ^= 1; }
        const float4* bufc = cur ? buf1 : buf0;

        // ---- absmax reduce from smem ----
        float m = 0.0f;
#pragma unroll
        for (int i = 0; i < CH; i++) {
            const float4 a = bufc[tid + i * NT];
            m = fmaxf(m, fmaxf(fmaxf(fabsf(a.x), fabsf(a.y)),
                               fmaxf(fabsf(a.z), fabsf(a.w))));
        }
#pragma unroll
        for (int o = 16; o; o >>= 1) m = fmaxf(m, __shfl_xor_sync(0xffffffffu, m, o));
        if (lane == 0) wmax[tid >> 5] = m;
        __syncthreads();     // also: all threads done with prev pass B (buf[nxt] free)
        float s = wmax[0];
#pragma unroll
        for (int i = 1; i < NT / 32; i++) s = fmaxf(s, wmax[i]);
        s = fmaxf(s, 1e-6f);                  // jnp.clip(..., 1e-6)
        const float c1 = __fdiv_rn(128.0f, s);

        // ---- issue TMA for next row into the other buffer (safe: barrier above) ----
        const int rn = r + GRID;
        if (tid == 0 && rn < rows) {
            const uint32_t nb = cur ? mbarA0 : mbarA1;
            const uint32_t nd = cur ? (sbase + OFF_BUF0) : (sbase + OFF_BUF1);
            mbar_expect_tx(nb, ROWB);
            tma_bulk_g2s(nd, x + (size_t)rn * COLS, ROWB, nb);
        }

        // ---- exact thresholds + scaled levels ----
        if (tid < NB) {
            const float mid = __ldg(bnd + tid);
            float t = mid * s;
            for (int it = 0; it < 8 && __fdiv_rn(t, s) <= mid; it++)
                t = nextafterf(t, __int_as_float(0x7f800000));
            for (int it = 0; it < 8 && __fdiv_rn(t, s) > mid; it++)
                t = nextafterf(t, __int_as_float(0xff800000));
            Tsm[tid] = t;
        }
        if (tid >= 32 && tid < 32 + NL)
            Vsm[tid - 32] = __ldg(dt + tid - 32) * s;   // RN, matches dt[idx]*s
        __syncthreads();

        // ---- build 258-cell LUT ----
        {
            const float w = s * 0.0078125f;   // s/128
            const float padc = 0.05f * w;
            for (int k = tid; k < NCELL; k += NT) {
                const float L = ((float)k - 129.5f) * w - padc;
                const float R = ((float)k - 128.5f) * w + padc;
                int jb = 0;
#pragma unroll
                for (int jj = 0; jj < NB; jj++) jb += (Tsm[jj] < L) ? 1 : 0;
                float T = __int_as_float(0x7f800000);
                float vlo, vhi;
                if (jb < NB && Tsm[jb] <= R) {
                    T = Tsm[jb]; vlo = Vsm[jb]; vhi = Vsm[jb + 1];
                } else {
                    vlo = vhi = Vsm[jb];
                }
                table[k] = make_float4(T, vlo, vhi, 0.0f);
            }
        }
        __syncthreads();

        // ---- pass B: quantize from smem, store row ----
        {
            float4* wp = (float4*)(out + (size_t)r * COLS);
#pragma unroll
            for (int i = 0; i < CH; i++) {
                const float4 b = bufc[tid + i * NT];
                float4 q;
                {
                    const int k = __float_as_int(fmaf(b.x, c1, MAGIC)) & 0x3ff;
                    const float4 e = table[k];
                    q.x = (b.x > e.x) ? e.z : e.y;
                }
                {
                    const int k = __float_as_int(fmaf(b.y, c1, MAGIC)) & 0x3ff;
                    const float4 e = table[k];
                    q.y = (b.y > e.x) ? e.z : e.y;
                }
                {
                    const int k = __float_as_int(fmaf(b.z, c1, MAGIC)) & 0x3ff;
                    const float4 e = table[k];
                    q.z = (b.z > e.x) ? e.z : e.y;
                }
                {
                    const int k = __float_as_int(fmaf(b.w, c1, MAGIC)) & 0x3ff;
                    const float4 e = table[k];
                    q.w = (b.w > e.x) ? e.z : e.y;
                }
                wp[tid + i * NT] = q;
            }
        }

        if (rn >= rows) break;
        r = rn;
        cur ^= 1;
    }
}

extern "C" void kernel_launch(void* const* d_in, const int* in_sizes, int n_in,
                              void* d_out, int out_size)
{
    const float* x = nullptr;
    const float* bnd = nullptr;
    const float* dt = nullptr;
    long long nx = 0;
    for (int i = 0; i < n_in; i++) {
        if (in_sizes[i] == NB)      bnd = (const float*)d_in[i];
        else if (in_sizes[i] == NL) dt  = (const float*)d_in[i];
        else { x = (const float*)d_in[i]; nx = in_sizes[i]; }
    }
    const int rows = (int)(nx / COLS);
    const int grid = rows < GRID ? rows : GRID;

    // idempotent; host-side, not a stream op (graph-capture safe)
    cudaFuncSetAttribute(nf4_kernel, cudaFuncAttributeMaxDynamicSharedMemorySize, SMEM_SZ);

    nf4_kernel<<<grid, NT, SMEM_SZ>>>(x, bnd, dt, (float*)d_out, rows);
}

// round 7
// speedup vs baseline: 1.1496x; 1.1496x over previous
#include <cuda_runtime.h>
#include <math.h>
#include <stdint.h>

// NF4 quantize-dequantize, straight-through forward: out = data_type[idx]*s,
// s = per-row max|x| (clip 1e-6), idx = searchsorted(boundaries, x/s, left).
//
// R7: R5 structure (best so far) with more concurrency and L2 hygiene.
//  - 128-thread blocks, 10/SM (1480 persistent blocks): 2x independent row
//    pipelines vs R5 -> more latency overlap (kernel is latency-bound).
//  - dynamic row claiming via device counter (init kernel) -> no ragged tail.
//  - st.global.cs streaming stores -> write stream doesn't evict pass-A rows
//    from L2, so pass-B re-reads stay L2 hits.
//  - float4 LUT entry -> one LDS.128 per element.
//
// Exactness (proven, unchanged): thresholds T_j = largest float with
// RN(t/s) <= b_j (nextafter-refined) => (x/s > b_j) == (x > T_j) bit-exact.
// 258-cell LUT over u = x*(128/s)+129 via magic-FMA; cell width s/128 <<
// min threshold gap (~0.085*s) => <=1 threshold per cell.

#define COLS   8192
#define NF4    2048          // float4 per row
#define NT     128
#define CH     16            // float4 per thread per row (2048/128)
#define NB     15
#define NL     16
#define NCELL  258
#define GRID   1480          // 10 blocks/SM x 148 SMs

__device__ int g_row_counter;

__global__ void init_counter_kernel(int start) { g_row_counter = start; }

__device__ __forceinline__ void stg_cs(float4* p, float4 v) {
    asm volatile("st.global.cs.v4.f32 [%0], {%1,%2,%3,%4};"
                 :: "l"(p), "f"(v.x), "f"(v.y), "f"(v.z), "f"(v.w) : "memory");
}

__global__ __launch_bounds__(NT, 10)
void nf4_kernel(const float* __restrict__ x,
                const float* __restrict__ bnd,
                const float* __restrict__ dt,
                float* __restrict__ out,
                int rows)
{
    __shared__ float4 table[NCELL];   // {T, vlo, vhi, pad}
    __shared__ float Tsm[NB];
    __shared__ float Vsm[NL];
    __shared__ float wmax[NT / 32];
    __shared__ int rnS;

    const int tid = threadIdx.x;
    const int lane = tid & 31;
    const float4* __restrict__ xv = (const float4*)x;
    float4* __restrict__ ov = (float4*)out;
    const float MAGIC = 8388608.0f + 129.0f;   // 2^23 + 129

    int r = blockIdx.x;           // grid <= rows guaranteed by launcher
    if (r >= rows) return;

    // ---- pass A, first row: streaming absmax ----
    float m = 0.0f;
    {
        const float4* rp = xv + (size_t)r * NF4;
#pragma unroll 4
        for (int i = 0; i < CH; i++) {
            const float4 a = __ldg(rp + tid + i * NT);
            m = fmaxf(m, fmaxf(fmaxf(fabsf(a.x), fabsf(a.y)),
                               fmaxf(fabsf(a.z), fabsf(a.w))));
        }
    }

    while (true) {
        // ---- block reduce -> s ----
#pragma unroll
        for (int o = 16; o; o >>= 1) m = fmaxf(m, __shfl_xor_sync(0xffffffffu, m, o));
        __syncthreads();               // prior iter's table/rnS readers done
        if (lane == 0) wmax[tid >> 5] = m;
        // claim next row while reduce settles
        if (tid == 64) rnS = atomicAdd(&g_row_counter, 1);
        __syncthreads();
        float s = fmaxf(fmaxf(wmax[0], wmax[1]), fmaxf(wmax[2], wmax[3]));
        s = fmaxf(s, 1e-6f);           // jnp.clip(..., 1e-6)
        const float c1 = __fdiv_rn(128.0f, s);

        // ---- exact raw-x thresholds + scaled levels ----
        if (tid < NB) {
            const float mid = __ldg(bnd + tid);
            float t = mid * s;
            for (int it = 0; it < 8 && __fdiv_rn(t, s) <= mid; it++)
                t = nextafterf(t, __int_as_float(0x7f800000));
            for (int it = 0; it < 8 && __fdiv_rn(t, s) > mid; it++)
                t = nextafterf(t, __int_as_float(0xff800000));
            Tsm[tid] = t;
        }
        if (tid >= 32 && tid < 32 + NL)
            Vsm[tid - 32] = __ldg(dt + tid - 32) * s;   // RN, matches dt[idx]*s
        __syncthreads();

        // ---- build 258-cell LUT ----
        {
            const float w = s * 0.0078125f;   // s/128
            const float padc = 0.05f * w;
#pragma unroll
            for (int k0 = 0; k0 < 3; k0++) {
                const int k = tid + k0 * NT;
                if (k < NCELL) {
                    const float L = ((float)k - 129.5f) * w - padc;
                    const float R = ((float)k - 128.5f) * w + padc;
                    int jb = 0;
#pragma unroll
                    for (int jj = 0; jj < NB; jj++) jb += (Tsm[jj] < L) ? 1 : 0;
                    float T = __int_as_float(0x7f800000);
                    float vlo, vhi;
                    if (jb < NB && Tsm[jb] <= R) {
                        T = Tsm[jb]; vlo = Vsm[jb]; vhi = Vsm[jb + 1];
                    } else {
                        vlo = vhi = Vsm[jb];
                    }
                    table[k] = make_float4(T, vlo, vhi, 0.0f);
                }
            }
        }
        __syncthreads();

        const int rn = rnS;
        const float4* rpB = xv + (size_t)r * NF4;   // L2 hit (read in pass A)
        float4* wp = ov + (size_t)r * NF4;

        if (rn < rows) {
            // ---- interleaved: pass A of row rn (DRAM) + pass B of row r ----
            const float4* rpA = xv + (size_t)rn * NF4;
            float mn = 0.0f;
#pragma unroll 4
            for (int i = 0; i < CH; i++) {
                const float4 a = __ldg(rpA + tid + i * NT);   // DRAM read, next row
                const float4 b = __ldg(rpB + tid + i * NT);   // L2 hit, current row
                mn = fmaxf(mn, fmaxf(fmaxf(fabsf(a.x), fabsf(a.y)),
                                     fmaxf(fabsf(a.z), fabsf(a.w))));
                float4 q;
                {
                    const int k = __float_as_int(fmaf(b.x, c1, MAGIC)) & 0x3ff;
                    const float4 e = table[k];
                    q.x = (b.x > e.x) ? e.z : e.y;
                }
                {
                    const int k = __float_as_int(fmaf(b.y, c1, MAGIC)) & 0x3ff;
                    const float4 e = table[k];
                    q.y = (b.y > e.x) ? e.z : e.y;
                }
                {
                    const int k = __float_as_int(fmaf(b.z, c1, MAGIC)) & 0x3ff;
                    const float4 e = table[k];
                    q.z = (b.z > e.x) ? e.z : e.y;
                }
                {
                    const int k = __float_as_int(fmaf(b.w, c1, MAGIC)) & 0x3ff;
                    const float4 e = table[k];
                    q.w = (b.w > e.x) ? e.z : e.y;
                }
                stg_cs(wp + tid + i * NT, q);   // streaming store: don't pollute L2
            }
            m = mn;
            r = rn;
        } else {
            // ---- final row for this block: pass B only ----
#pragma unroll 4
            for (int i = 0; i < CH; i++) {
                const float4 b = __ldg(rpB + tid + i * NT);
                float4 q;
                {
                    const int k = __float_as_int(fmaf(b.x, c1, MAGIC)) & 0x3ff;
                    const float4 e = table[k];
                    q.x = (b.x > e.x) ? e.z : e.y;
                }
                {
                    const int k = __float_as_int(fmaf(b.y, c1, MAGIC)) & 0x3ff;
                    const float4 e = table[k];
                    q.y = (b.y > e.x) ? e.z : e.y;
                }
                {
                    const int k = __float_as_int(fmaf(b.z, c1, MAGIC)) & 0x3ff;
                    const float4 e = table[k];
                    q.z = (b.z > e.x) ? e.z : e.y;
                }
                {
                    const int k = __float_as_int(fmaf(b.w, c1, MAGIC)) & 0x3ff;
                    const float4 e = table[k];
                    q.w = (b.w > e.x) ? e.z : e.y;
                }
                stg_cs(wp + tid + i * NT, q);
            }
            break;
        }
    }
}

extern "C" void kernel_launch(void* const* d_in, const int* in_sizes, int n_in,
                              void* d_out, int out_size)
{
    const float* x = nullptr;
    const float* bnd = nullptr;
    const float* dt = nullptr;
    long long nx = 0;
    for (int i = 0; i < n_in; i++) {
        if (in_sizes[i] == NB)      bnd = (const float*)d_in[i];
        else if (in_sizes[i] == NL) dt  = (const float*)d_in[i];
        else { x = (const float*)d_in[i]; nx = in_sizes[i]; }
    }
    const int rows = (int)(nx / COLS);
    const int grid = rows < GRID ? rows : GRID;

    init_counter_kernel<<<1, 1>>>(grid);   // first `grid` rows claimed statically
    nf4_kernel<<<grid, NT>>>(x, bnd, dt, (float*)d_out, rows);
}

// round 8
// speedup vs baseline: 1.1506x; 1.0009x over previous
#include <cuda_runtime.h>
#include <math.h>
#include <stdint.h>

// NF4 quantize-dequantize, straight-through forward: out = data_type[idx]*s,
// s = per-row max|x| (clip 1e-6), idx = searchsorted(boundaries, x/s, left).
//
// R8: single-DRAM-read design. Each block stages its row in a 32KB shared
// buffer during the absmax pass (LDG->STS fused with max); the quantize pass
// reads smem, not L2. Total DRAM traffic = 512MB regardless of concurrency
// (R7 showed the L2-re-read scheme loses residency as concurrency grows).
// 6 blocks/SM x 256 threads, dynamic row claiming, prefetch.global.L2 of the
// next row during quantize (overlaps next-row DRAM read with current-row
// stores), .cs streaming stores.
//
// Exactness (proven, unchanged): thresholds T_j = largest float with
// RN(t/s) <= b_j (nextafter-refined) => (x/s > b_j) == (x > T_j) bit-exact.
// 258-cell LUT over u = x*(128/s)+129 via magic-FMA; cell width s/128 <<
// min threshold gap (~0.085*s) => <=1 threshold per cell. float4 entry ->
// one LDS.128 per element.

#define COLS   8192
#define NF4    2048          // float4 per row
#define NT     256
#define CH     8             // float4 per thread per row (2048/256)
#define NB     15
#define NL     16
#define NCELL  258
#define GRID   888           // 6 blocks/SM x 148 SMs

__device__ int g_row_counter;

__global__ void init_counter_kernel(int start) { g_row_counter = start; }

__device__ __forceinline__ void stg_cs(float4* p, float4 v) {
    asm volatile("st.global.cs.v4.f32 [%0], {%1,%2,%3,%4};"
                 :: "l"(p), "f"(v.x), "f"(v.y), "f"(v.z), "f"(v.w) : "memory");
}
__device__ __forceinline__ void prefetch_l2(const void* p) {
    asm volatile("prefetch.global.L2 [%0];" :: "l"(p));
}

__global__ __launch_bounds__(NT, 6)
void nf4_kernel(const float* __restrict__ x,
                const float* __restrict__ bnd,
                const float* __restrict__ dt,
                float* __restrict__ out,
                int rows)
{
    __shared__ float4 sbuf[NF4];      // 32KB row buffer
    __shared__ float4 table[NCELL];   // {T, vlo, vhi, pad}
    __shared__ float Tsm[NB];
    __shared__ float Vsm[NL];
    __shared__ float wmax[NT / 32];
    __shared__ int rnS;

    const int tid = threadIdx.x;
    const int lane = tid & 31;
    const float4* __restrict__ xv = (const float4*)x;
    float4* __restrict__ ov = (float4*)out;
    const float MAGIC = 8388608.0f + 129.0f;   // 2^23 + 129

    int r = blockIdx.x;               // launcher guarantees grid <= rows
    if (r >= rows) return;

    while (true) {
        // ---- pass A: stream row into smem, fused absmax ----
        float m = 0.0f;
        {
            const float4* rp = xv + (size_t)r * NF4;
#pragma unroll 4
            for (int i = 0; i < CH; i++) {
                const float4 a = __ldg(rp + tid + i * NT);
                sbuf[tid + i * NT] = a;
                m = fmaxf(m, fmaxf(fmaxf(fabsf(a.x), fabsf(a.y)),
                                   fmaxf(fabsf(a.z), fabsf(a.w))));
            }
        }
#pragma unroll
        for (int o = 16; o; o >>= 1) m = fmaxf(m, __shfl_xor_sync(0xffffffffu, m, o));
        if (lane == 0) wmax[tid >> 5] = m;
        if (tid == 64) rnS = atomicAdd(&g_row_counter, 1);   // claim next row
        __syncthreads();
        float s = fmaxf(fmaxf(fmaxf(wmax[0], wmax[1]), fmaxf(wmax[2], wmax[3])),
                        fmaxf(fmaxf(wmax[4], wmax[5]), fmaxf(wmax[6], wmax[7])));
        s = fmaxf(s, 1e-6f);          // jnp.clip(..., 1e-6)
        const float c1 = __fdiv_rn(128.0f, s);

        // ---- exact raw-x thresholds + scaled levels ----
        if (tid < NB) {
            const float mid = __ldg(bnd + tid);
            float t = mid * s;
            for (int it = 0; it < 8 && __fdiv_rn(t, s) <= mid; it++)
                t = nextafterf(t, __int_as_float(0x7f800000));
            for (int it = 0; it < 8 && __fdiv_rn(t, s) > mid; it++)
                t = nextafterf(t, __int_as_float(0xff800000));
            Tsm[tid] = t;
        }
        if (tid >= 32 && tid < 32 + NL)
            Vsm[tid - 32] = __ldg(dt + tid - 32) * s;   // RN, matches dt[idx]*s
        __syncthreads();

        // ---- build 258-cell LUT ----
        {
            const float w = s * 0.0078125f;   // s/128
            const float padc = 0.05f * w;
#pragma unroll
            for (int k0 = 0; k0 < 2; k0++) {
                const int k = tid + k0 * NT;
                if (k < NCELL) {
                    const float L = ((float)k - 129.5f) * w - padc;
                    const float R = ((float)k - 128.5f) * w + padc;
                    int jb = 0;
#pragma unroll
                    for (int jj = 0; jj < NB; jj++) jb += (Tsm[jj] < L) ? 1 : 0;
                    float T = __int_as_float(0x7f800000);
                    float vlo, vhi;
                    if (jb < NB && Tsm[jb] <= R) {
                        T = Tsm[jb]; vlo = Vsm[jb]; vhi = Vsm[jb + 1];
                    } else {
                        vlo = vhi = Vsm[jb];
                    }
                    table[k] = make_float4(T, vlo, vhi, 0.0f);
                }
            }
        }
        __syncthreads();

        const int rn = rnS;

        // ---- prefetch next row to L2 (no regs, overlaps quantize+stores) ----
        if (rn < rows) {
            const char* np = (const char*)(xv + (size_t)rn * NF4);
            prefetch_l2(np + tid * 128);     // 256 threads x 128B = full 32KB row
        }

        // ---- pass B: quantize from smem, streaming-store row ----
        {
            float4* wp = ov + (size_t)r * NF4;
#pragma unroll 4
            for (int i = 0; i < CH; i++) {
                const float4 b = sbuf[tid + i * NT];
                float4 q;
                {
                    const int k = __float_as_int(fmaf(b.x, c1, MAGIC)) & 0x3ff;
                    const float4 e = table[k];
                    q.x = (b.x > e.x) ? e.z : e.y;
                }
                {
                    const int k = __float_as_int(fmaf(b.y, c1, MAGIC)) & 0x3ff;
                    const float4 e = table[k];
                    q.y = (b.y > e.x) ? e.z : e.y;
                }
                {
                    const int k = __float_as_int(fmaf(b.z, c1, MAGIC)) & 0x3ff;
                    const float4 e = table[k];
                    q.z = (b.z > e.x) ? e.z : e.y;
                }
                {
                    const int k = __float_as_int(fmaf(b.w, c1, MAGIC)) & 0x3ff;
                    const float4 e = table[k];
                    q.w = (b.w > e.x) ? e.z : e.y;
                }
                stg_cs(wp + tid + i * NT, q);
            }
        }

        if (rn >= rows) break;
        r = rn;
        __syncthreads();   // sbuf readers done before next pass A overwrites
    }
}

extern "C" void kernel_launch(void* const* d_in, const int* in_sizes, int n_in,
                              void* d_out, int out_size)
{
    const float* x = nullptr;
    const float* bnd = nullptr;
    const float* dt = nullptr;
    long long nx = 0;
    for (int i = 0; i < n_in; i++) {
        if (in_sizes[i] == NB)      bnd = (const float*)d_in[i];
        else if (in_sizes[i] == NL) dt  = (const float*)d_in[i];
        else { x = (const float*)d_in[i]; nx = in_sizes[i]; }
    }
    const int rows = (int)(nx / COLS);
    const int grid = rows < GRID ? rows : GRID;

    init_counter_kernel<<<1, 1>>>(grid);   // rows [0, grid) claimed statically
    nf4_kernel<<<grid, NT>>>(x, bnd, dt, (float*)d_out, rows);
}

// round 10
// speedup vs baseline: 1.4100x; 1.2254x over previous
#include <cuda_runtime.h>
#include <math.h>
#include <stdint.h>

// NF4 quantize-dequantize, straight-through forward: out = data_type[idx]*s,
// s = per-row max|x| (clip 1e-6), idx = searchsorted(boundaries, x/s, left).
//
// R9 (resubmit; prior run was an infra failure): minimize L1tex bytes/elem
// (R8 hit the L1 wall at 89.5% with ideal DRAM traffic).
//  - Row held in REGISTERS (16/thread @ NT=512): no smem staging round-trip.
//  - Split 8B table: Tarr[k] (LDS.32) + Vint[2k + (x>T)] (LDS.32).
//  - L1 per elem: LDG 4 + table 8 + STG 4 = 16B (was 32B in R8).
//  - 3 blocks/SM x 512 thr (launch_bounds(512,3), ~42 regs) -> 75% occ,
//    3 independent row pipelines per SM.
//  - Dynamic row claiming, .cs streaming stores, L2-prefetch of next row
//    during quantize (read/write DRAM overlap, zero register cost).
//
// Exactness (proven): thresholds T_j = largest float with RN(t/s) <= b_j
// (nextafter-refined) => (x/s > b_j) == (x > T_j) bit-exact. 258-cell LUT
// over u = x*(128/s)+129 via magic-FMA; cell width s/128 << min threshold
// gap (~0.085*s) => <=1 threshold per cell.

#define COLS   8192
#define NF4    2048          // float4 per row
#define NT     512
#define CH     4             // float4 per thread per row (2048/512)
#define NB     15
#define NL     16
#define NCELL  258
#define GRID   444           // 3 blocks/SM x 148 SMs

__device__ int g_row_counter;

__global__ void init_counter_kernel(int start) { g_row_counter = start; }

__device__ __forceinline__ void stg_cs(float4* p, float4 v) {
    asm volatile("st.global.cs.v4.f32 [%0], {%1,%2,%3,%4};"
                 :: "l"(p), "f"(v.x), "f"(v.y), "f"(v.z), "f"(v.w) : "memory");
}
__device__ __forceinline__ void prefetch_l2(const void* p) {
    asm volatile("prefetch.global.L2 [%0];" :: "l"(p));
}

__global__ __launch_bounds__(NT, 3)
void nf4_kernel(const float* __restrict__ x,
                const float* __restrict__ bnd,
                const float* __restrict__ dt,
                float* __restrict__ out,
                int rows)
{
    __shared__ float Tarr[NCELL];       // threshold per cell
    __shared__ float Vint[2 * NCELL];   // {vlo, vhi} per cell
    __shared__ float Tsm[NB];
    __shared__ float Vsm[NL];
    __shared__ float wmax[NT / 32];
    __shared__ int rnS;

    const int tid = threadIdx.x;
    const int lane = tid & 31;
    const float4* __restrict__ xv = (const float4*)x;
    float4* __restrict__ ov = (float4*)out;
    const float MAGIC = 8388608.0f + 129.0f;   // 2^23 + 129

    int r = blockIdx.x;                 // launcher guarantees grid <= rows
    if (r >= rows) return;

    while (true) {
        // ---- pass A: row -> registers, fused absmax ----
        float4 va[CH];
        float m = 0.0f;
        {
            const float4* rp = xv + (size_t)r * NF4;
#pragma unroll
            for (int i = 0; i < CH; i++) {
                va[i] = __ldg(rp + tid + i * NT);
                m = fmaxf(m, fmaxf(fmaxf(fabsf(va[i].x), fabsf(va[i].y)),
                                   fmaxf(fabsf(va[i].z), fabsf(va[i].w))));
            }
        }
#pragma unroll
        for (int o = 16; o; o >>= 1) m = fmaxf(m, __shfl_xor_sync(0xffffffffu, m, o));
        if (lane == 0) wmax[tid >> 5] = m;
        if (tid == 64) rnS = atomicAdd(&g_row_counter, 1);   // claim next row
        __syncthreads();    // also: prev iter's table readers are done
        float s;
        {
            float t0 = fmaxf(fmaxf(wmax[0], wmax[1]),  fmaxf(wmax[2], wmax[3]));
            float t1 = fmaxf(fmaxf(wmax[4], wmax[5]),  fmaxf(wmax[6], wmax[7]));
            float t2 = fmaxf(fmaxf(wmax[8], wmax[9]),  fmaxf(wmax[10], wmax[11]));
            float t3 = fmaxf(fmaxf(wmax[12], wmax[13]), fmaxf(wmax[14], wmax[15]));
            s = fmaxf(fmaxf(t0, t1), fmaxf(t2, t3));
        }
        s = fmaxf(s, 1e-6f);            // jnp.clip(..., 1e-6)
        const float c1 = __fdiv_rn(128.0f, s);

        // ---- exact raw-x thresholds + scaled levels ----
        if (tid < NB) {
            const float mid = __ldg(bnd + tid);
            float t = mid * s;
            for (int it = 0; it < 8 && __fdiv_rn(t, s) <= mid; it++)
                t = nextafterf(t, __int_as_float(0x7f800000));
            for (int it = 0; it < 8 && __fdiv_rn(t, s) > mid; it++)
                t = nextafterf(t, __int_as_float(0xff800000));
            Tsm[tid] = t;
        }
        if (tid >= 32 && tid < 32 + NL)
            Vsm[tid - 32] = __ldg(dt + tid - 32) * s;   // RN, matches dt[idx]*s
        __syncthreads();

        // ---- build split LUT: Tarr + interleaved value pairs ----
        if (tid < NCELL) {
            const float w = s * 0.0078125f;   // s/128
            const float padc = 0.05f * w;
            const float L = ((float)tid - 129.5f) * w - padc;
            const float R = ((float)tid - 128.5f) * w + padc;
            int jb = 0;
#pragma unroll
            for (int jj = 0; jj < NB; jj++) jb += (Tsm[jj] < L) ? 1 : 0;
            float T = __int_as_float(0x7f800000);
            float vlo, vhi;
            if (jb < NB && Tsm[jb] <= R) {
                T = Tsm[jb]; vlo = Vsm[jb]; vhi = Vsm[jb + 1];
            } else {
                vlo = vhi = Vsm[jb];
            }
            Tarr[tid] = T;
            Vint[2 * tid]     = vlo;
            Vint[2 * tid + 1] = vhi;
        }
        __syncthreads();

        const int rn = rnS;

        // ---- L2 prefetch of next row (512 thr x 64B = 32KB) ----
        if (rn < rows) {
            const char* np = (const char*)(xv + (size_t)rn * NF4);
            prefetch_l2(np + (size_t)tid * 64);
        }

        // ---- pass B: quantize from registers, streaming-store ----
        {
            float4* wp = ov + (size_t)r * NF4;
#pragma unroll
            for (int i = 0; i < CH; i++) {
                const float4 b = va[i];
                float4 q;
                {
                    const int k = __float_as_int(fmaf(b.x, c1, MAGIC)) & 0x3ff;
                    q.x = Vint[2 * k + ((b.x > Tarr[k]) ? 1 : 0)];
                }
                {
                    const int k = __float_as_int(fmaf(b.y, c1, MAGIC)) & 0x3ff;
                    q.y = Vint[2 * k + ((b.y > Tarr[k]) ? 1 : 0)];
                }
                {
                    const int k = __float_as_int(fmaf(b.z, c1, MAGIC)) & 0x3ff;
                    q.z = Vint[2 * k + ((b.z > Tarr[k]) ? 1 : 0)];
                }
                {
                    const int k = __float_as_int(fmaf(b.w, c1, MAGIC)) & 0x3ff;
                    q.w = Vint[2 * k + ((b.w > Tarr[k]) ? 1 : 0)];
                }
                stg_cs(wp + tid + i * NT, q);
            }
        }

        if (rn >= rows) break;
        r = rn;
    }
}

extern "C" void kernel_launch(void* const* d_in, const int* in_sizes, int n_in,
                              void* d_out, int out_size)
{
    const float* x = nullptr;
    const float* bnd = nullptr;
    const float* dt = nullptr;
    long long nx = 0;
    for (int i = 0; i < n_in; i++) {
        if (in_sizes[i] == NB)      bnd = (const float*)d_in[i];
        else if (in_sizes[i] == NL) dt  = (const float*)d_in[i];
        else { x = (const float*)d_in[i]; nx = in_sizes[i]; }
    }
    const int rows = (int)(nx / COLS);
    const int grid = rows < GRID ? rows : GRID;

    init_counter_kernel<<<1, 1>>>(grid);   // rows [0, grid) claimed statically
    nf4_kernel<<<grid, NT>>>(x, bnd, dt, (float*)d_out, rows);
}

// round 12
// speedup vs baseline: 1.4930x; 1.0588x over previous
#include <cuda_runtime.h>
#include <math.h>
#include <stdint.h>

// NF4 quantize-dequantize, straight-through forward: out = data_type[idx]*s,
// s = per-row max|x| (clip 1e-6), idx = searchsorted(boundaries, x/s, left).
//
// R11 (resubmit; prior run was an infra failure) = R10 (winner, 110.6us) + two fixes:
//  - Value table layout Vtab[k + 264*sel] (was [2k+sel]): sel==0 for the 243
//    non-boundary cells made addresses even-bank-only -> 2x LDS conflicts.
//    New layout spreads over all 32 banks.
//  - L2 prefetch of the next claimed row moved up to right after the scale
//    reduce (was after LUT build): next-row DRAM read now overlaps the
//    serial threshold/LUT phase AND pass B, not just pass B.
// Proven and kept: row in registers (16/thread @ NT=512), 8B table path,
// 3 blocks/SM (launch_bounds(512,3), 40 regs), dynamic row claiming,
// .cs streaming stores.
//
// Exactness (proven): thresholds T_j = largest float with RN(t/s) <= b_j
// (nextafter-refined) => (x/s > b_j) == (x > T_j) bit-exact. 258-cell LUT
// over u = x*(128/s)+129 via magic-FMA; cell width s/128 << min threshold
// gap (~0.085*s) => <=1 threshold per cell.

#define COLS   8192
#define NF4    2048          // float4 per row
#define NT     512
#define CH     4             // float4 per thread per row (2048/512)
#define NB     15
#define NL     16
#define NCELL  258
#define NPAD   264           // value-table stride (mod 32 == 8: full-bank)
#define GRID   444           // 3 blocks/SM x 148 SMs

__device__ int g_row_counter;

__global__ void init_counter_kernel(int start) { g_row_counter = start; }

__device__ __forceinline__ void stg_cs(float4* p, float4 v) {
    asm volatile("st.global.cs.v4.f32 [%0], {%1,%2,%3,%4};"
                 :: "l"(p), "f"(v.x), "f"(v.y), "f"(v.z), "f"(v.w) : "memory");
}
__device__ __forceinline__ void prefetch_l2(const void* p) {
    asm volatile("prefetch.global.L2 [%0];" :: "l"(p));
}

__global__ __launch_bounds__(NT, 3)
void nf4_kernel(const float* __restrict__ x,
                const float* __restrict__ bnd,
                const float* __restrict__ dt,
                float* __restrict__ out,
                int rows)
{
    __shared__ float Tarr[NCELL];         // threshold per cell
    __shared__ float Vtab[2 * NPAD];      // [k + NPAD*sel]
    __shared__ float Tsm[NB];
    __shared__ float Vsm[NL];
    __shared__ float wmax[NT / 32];
    __shared__ int rnS;

    const int tid = threadIdx.x;
    const int lane = tid & 31;
    const float4* __restrict__ xv = (const float4*)x;
    float4* __restrict__ ov = (float4*)out;
    const float MAGIC = 8388608.0f + 129.0f;   // 2^23 + 129

    int r = blockIdx.x;                 // launcher guarantees grid <= rows
    if (r >= rows) return;

    while (true) {
        // ---- pass A: row -> registers, fused absmax ----
        float4 va[CH];
        float m = 0.0f;
        {
            const float4* rp = xv + (size_t)r * NF4;
#pragma unroll
            for (int i = 0; i < CH; i++) {
                va[i] = __ldg(rp + tid + i * NT);
                m = fmaxf(m, fmaxf(fmaxf(fabsf(va[i].x), fabsf(va[i].y)),
                                   fmaxf(fabsf(va[i].z), fabsf(va[i].w))));
            }
        }
#pragma unroll
        for (int o = 16; o; o >>= 1) m = fmaxf(m, __shfl_xor_sync(0xffffffffu, m, o));
        if (lane == 0) wmax[tid >> 5] = m;
        if (tid == 64) rnS = atomicAdd(&g_row_counter, 1);   // claim next row
        __syncthreads();    // also: prev iter's table readers are done
        float s;
        {
            float t0 = fmaxf(fmaxf(wmax[0], wmax[1]),  fmaxf(wmax[2], wmax[3]));
            float t1 = fmaxf(fmaxf(wmax[4], wmax[5]),  fmaxf(wmax[6], wmax[7]));
            float t2 = fmaxf(fmaxf(wmax[8], wmax[9]),  fmaxf(wmax[10], wmax[11]));
            float t3 = fmaxf(fmaxf(wmax[12], wmax[13]), fmaxf(wmax[14], wmax[15]));
            s = fmaxf(fmaxf(t0, t1), fmaxf(t2, t3));
        }
        s = fmaxf(s, 1e-6f);            // jnp.clip(..., 1e-6)
        const float c1 = __fdiv_rn(128.0f, s);

        // ---- L2 prefetch of next row NOW: overlaps threshold/LUT + pass B ----
        const int rn = rnS;
        if (rn < rows) {
            const char* np = (const char*)(xv + (size_t)rn * NF4);
            prefetch_l2(np + (size_t)tid * 64);   // 512 thr x 64B = 32KB row
        }

        // ---- exact raw-x thresholds + scaled levels ----
        if (tid < NB) {
            const float mid = __ldg(bnd + tid);
            float t = mid * s;
            for (int it = 0; it < 8 && __fdiv_rn(t, s) <= mid; it++)
                t = nextafterf(t, __int_as_float(0x7f800000));
            for (int it = 0; it < 8 && __fdiv_rn(t, s) > mid; it++)
                t = nextafterf(t, __int_as_float(0xff800000));
            Tsm[tid] = t;
        }
        if (tid >= 32 && tid < 32 + NL)
            Vsm[tid - 32] = __ldg(dt + tid - 32) * s;   // RN, matches dt[idx]*s
        __syncthreads();

        // ---- build split LUT: Tarr + full-bank value table ----
        if (tid < NCELL) {
            const float w = s * 0.0078125f;   // s/128
            const float padc = 0.05f * w;
            const float L = ((float)tid - 129.5f) * w - padc;
            const float R = ((float)tid - 128.5f) * w + padc;
            int jb = 0;
#pragma unroll
            for (int jj = 0; jj < NB; jj++) jb += (Tsm[jj] < L) ? 1 : 0;
            float T = __int_as_float(0x7f800000);
            float vlo, vhi;
            if (jb < NB && Tsm[jb] <= R) {
                T = Tsm[jb]; vlo = Vsm[jb]; vhi = Vsm[jb + 1];
            } else {
                vlo = vhi = Vsm[jb];
            }
            Tarr[tid] = T;
            Vtab[tid]        = vlo;
            Vtab[tid + NPAD] = vhi;
        }
        __syncthreads();

        // ---- pass B: quantize from registers, streaming-store ----
        {
            float4* wp = ov + (size_t)r * NF4;
#pragma unroll
            for (int i = 0; i < CH; i++) {
                const float4 b = va[i];
                float4 q;
                {
                    const int k = __float_as_int(fmaf(b.x, c1, MAGIC)) & 0x3ff;
                    q.x = Vtab[k + ((b.x > Tarr[k]) ? NPAD : 0)];
                }
                {
                    const int k = __float_as_int(fmaf(b.y, c1, MAGIC)) & 0x3ff;
                    q.y = Vtab[k + ((b.y > Tarr[k]) ? NPAD : 0)];
                }
                {
                    const int k = __float_as_int(fmaf(b.z, c1, MAGIC)) & 0x3ff;
                    q.z = Vtab[k + ((b.z > Tarr[k]) ? NPAD : 0)];
                }
                {
                    const int k = __float_as_int(fmaf(b.w, c1, MAGIC)) & 0x3ff;
                    q.w = Vtab[k + ((b.w > Tarr[k]) ? NPAD : 0)];
                }
                stg_cs(wp + tid + i * NT, q);
            }
        }

        if (rn >= rows) break;
        r = rn;
    }
}

extern "C" void kernel_launch(void* const* d_in, const int* in_sizes, int n_in,
                              void* d_out, int out_size)
{
    const float* x = nullptr;
    const float* bnd = nullptr;
    const float* dt = nullptr;
    long long nx = 0;
    for (int i = 0; i < n_in; i++) {
        if (in_sizes[i] == NB)      bnd = (const float*)d_in[i];
        else if (in_sizes[i] == NL) dt  = (const float*)d_in[i];
        else { x = (const float*)d_in[i]; nx = in_sizes[i]; }
    }
    const int rows = (int)(nx / COLS);
    const int grid = rows < GRID ? rows : GRID;

    init_counter_kernel<<<1, 1>>>(grid);   // rows [0, grid) claimed statically
    nf4_kernel<<<grid, NT>>>(x, bnd, dt, (float*)d_out, rows);
}